// round 3
// baseline (speedup 1.0000x reference)
#include <cuda_runtime.h>
#include <cuda_bf16.h>

#define Ww      512
#define HW      (512*512)
#define RROWS   21
#define CHUNKS  24
#define NPLANES 24
#define GRID    (NPLANES*CHUNKS)      // 504 blocks... actually 576
#define XROWS   502                   // gx box rows
#define NOUTX   503                   // gx box cols
#define NOUTY   502                   // gy box cols
#define SPITCH  520

__device__ double g_part[GRID][3];    // ratio, gx, gy per block
__device__ unsigned int g_ctr = 0;    // last-block counter (self-resetting)

// running 10-sum, 13 outputs per thread, t in [0,39): stride 13 coprime to 32
// -> conflict-free. Max src index = 511 (arrays sized SPITCH>=512).
__device__ __forceinline__ void hsum13(const float* __restrict__ src,
                                       float* __restrict__ dst, int nOut, int t) {
    int base = 13 * t;
    if (base >= nOut) return;
    float s = 0.f;
#pragma unroll
    for (int k = 0; k < 10; k++) s += src[base + k];
#pragma unroll
    for (int u = 0; u < 13; u++) {
        int j = base + u;
        if (j >= nOut) break;
        dst[j] = s;
        if (u < 12 && j + 1 < nOut) s += src[j + 10] - src[j];
    }
}

__global__ __launch_bounds__(256)
void ktv_kernel(const float* __restrict__ outl,
                const float* __restrict__ outr,
                const float* __restrict__ inpi,
                float* __restrict__ out) {
    __shared__ float sV[6][SPITCH];      // Vx L/R/I = 0..2, Vy L/R/I = 3..5
    __shared__ float sSx[3][SPITCH];
    __shared__ float sSy[2][3][SPITCH];
    __shared__ float sred[3][8];
    __shared__ double dred[3][8];
    __shared__ unsigned s_rank;

    const int plane = blockIdx.x / CHUNKS;
    const int chunk = blockIdx.x % CHUNKS;
    const int r0 = chunk * RROWS;
    const int r1 = min(r0 + RROWS, XROWS);
    const bool is_last = (r1 == XROWS);
    const float* __restrict__ base[3] = {
        outl + (size_t)plane * HW,
        outr + (size_t)plane * HW,
        inpi + (size_t)plane * HW };
    const int c = threadIdx.x;             // column pair (2c, 2c+1)
    const int x2i = (c < 255) ? (2 * c + 2) : 511;   // clamped col+2 index
    const bool cok = (c < 255);            // gy valid at col 2c+1

    float accr = 0.f, accgx = 0.f, accgy = 0.f;
    float2 Vx[3], Vy[3], p[3], l[3], pt[3];
    float  lx2[3], ptx2[3];
#pragma unroll
    for (int j = 0; j < 3; j++) { Vx[j] = make_float2(0.f, 0.f); Vy[j] = make_float2(0.f, 0.f); }

    // ---- bootstrap rows r0..r0+10 ----
#pragma unroll 1
    for (int k = 0; k <= 10; k++) {
        const int row = r0 + k;
        float2 v[3]; float x2[3];
#pragma unroll
        for (int j = 0; j < 3; j++) {
            const float* rp = base[j] + (size_t)row * Ww;
            v[j]  = reinterpret_cast<const float2*>(rp)[c];
            x2[j] = rp[x2i];
        }
        if (k > 0) {
            float2 g[3];
#pragma unroll
            for (int j = 0; j < 3; j++) {
                g[j].x = v[j].x - p[j].x; g[j].y = v[j].y - p[j].y;
                Vx[j].x += fabsf(g[j].x); Vx[j].y += fabsf(g[j].y);
            }
            int gr = row - 1;
            if ((gr >= r0 && gr < r1) || (is_last && gr >= XROWS))
                accgx += fabsf(g[0].x + g[1].x - g[2].x)
                       + fabsf(g[0].y + g[1].y - g[2].y);
        }
        float2 y[3];
#pragma unroll
        for (int j = 0; j < 3; j++) {
            y[j].x = v[j].y - v[j].x;
            y[j].y = x2[j] - v[j].y;
        }
        if (k < 10) {
#pragma unroll
            for (int j = 0; j < 3; j++) { Vy[j].x += fabsf(y[j].x); Vy[j].y += fabsf(y[j].y); }
        }
        if ((row >= r0 && row < r1) || (is_last && row >= XROWS)) {
            accgy += fabsf(y[0].x + y[1].x - y[2].x);
            if (cok) accgy += fabsf(y[0].y + y[1].y - y[2].y);
        }
#pragma unroll
        for (int j = 0; j < 3; j++) p[j] = v[j];
        if (k == 0)  { for (int j = 0; j < 3; j++) { pt[j] = v[j]; ptx2[j] = x2[j]; } }
        if (k == 10) { for (int j = 0; j < 3; j++) { l[j]  = v[j]; lx2[j]  = x2[j]; } }
    }

    // hsum Vy(r0) -> sSy[0]
#pragma unroll
    for (int j = 0; j < 3; j++)
        *reinterpret_cast<float2*>(&sV[3 + j][2 * c]) = Vy[j];
    __syncthreads();
    if (c < 117) hsum13(sV[3 + c / 39], sSy[0][c / 39], NOUTY, c % 39);
    __syncthreads();
    int par = 0;   // sSy[par] = S_y(row r)

    // prefetch registers: pn = row r+10 for next iter, ptl = row r for next iter
    float2 pn[3], ptl[3]; float pnx2[3], ptlx2[3];

    // ---- main loop over output x-rows ----
    for (int r = r0; r < r1; r++) {
        float2 VyN[3];
        if (r == r0) {
            // lead = bootstrap row r0+10 (l,lx2); trail = row r0 (pt,ptx2); Vx unchanged
#pragma unroll
            for (int j = 0; j < 3; j++) {
                float2 ty; ty.x = pt[j].y - pt[j].x; ty.y = ptx2[j] - pt[j].y;
                float2 yl; yl.x = l[j].y - l[j].x;   yl.y = lx2[j]  - l[j].y;
                VyN[j].x = Vy[j].x - fabsf(ty.x) + fabsf(yl.x);
                VyN[j].y = Vy[j].y - fabsf(ty.y) + fabsf(yl.y);
            }
        } else {
            // pn = row r+10, ptl = row r (prefetched last iteration)
            float2 gl[3];
#pragma unroll
            for (int j = 0; j < 3; j++) {
                gl[j].x = pn[j].x - l[j].x;  gl[j].y = pn[j].y - l[j].y;
                float2 gt; gt.x = ptl[j].x - pt[j].x; gt.y = ptl[j].y - pt[j].y;
                Vx[j].x += fabsf(gl[j].x) - fabsf(gt.x);
                Vx[j].y += fabsf(gl[j].y) - fabsf(gt.y);
            }
            int g = r + 9;
            if ((g >= r0 && g < r1) || (is_last && g >= XROWS))
                accgx += fabsf(gl[0].x + gl[1].x - gl[2].x)
                       + fabsf(gl[0].y + gl[1].y - gl[2].y);
            float2 yl[3];
#pragma unroll
            for (int j = 0; j < 3; j++) {
                yl[j].x = pn[j].y - pn[j].x;   yl[j].y = pnx2[j] - pn[j].y;
                float2 ty; ty.x = ptl[j].y - ptl[j].x; ty.y = ptlx2[j] - ptl[j].y;
                VyN[j].x = Vy[j].x - fabsf(ty.x) + fabsf(yl[j].x);
                VyN[j].y = Vy[j].y - fabsf(ty.y) + fabsf(yl[j].y);
            }
            int gy = r + 10;
            if ((gy >= r0 && gy < r1) || (is_last && gy >= XROWS)) {
                accgy += fabsf(yl[0].x + yl[1].x - yl[2].x);
                if (cok) accgy += fabsf(yl[0].y + yl[1].y - yl[2].y);
            }
#pragma unroll
            for (int j = 0; j < 3; j++) { l[j] = pn[j]; lx2[j] = pnx2[j]; pt[j] = ptl[j]; }
        }

#pragma unroll
        for (int j = 0; j < 3; j++) {
            *reinterpret_cast<float2*>(&sV[j][2 * c])     = Vx[j];
            *reinterpret_cast<float2*>(&sV[3 + j][2 * c]) = VyN[j];
        }
        __syncthreads();

        // prefetch rows (r+11) and (r+1) for the next iteration; LDG latency
        // hides behind hsum + ratio work below.
        if (r + 1 < r1) {
#pragma unroll
            for (int j = 0; j < 3; j++) {
                const float* rpn = base[j] + (size_t)(r + 11) * Ww;
                const float* rpt = base[j] + (size_t)(r + 1) * Ww;
                pn[j]    = reinterpret_cast<const float2*>(rpn)[c];
                pnx2[j]  = rpn[x2i];
                ptl[j]   = reinterpret_cast<const float2*>(rpt)[c];
                ptlx2[j] = rpt[x2i];
            }
        }

        if (c < 234) {
            int a = c / 39, t = c % 39;
            if (a < 3) hsum13(sV[a], sSx[a], NOUTX, t);
            else       hsum13(sV[a], sSy[par ^ 1][a - 3], NOUTY, t);
        }
        __syncthreads();
#pragma unroll
        for (int oi = 0; oi < 2; oi++) {
            int o = c + oi * 256;
            if (o < NOUTX) {
                float Sxl = sSx[0][o], Sxr = sSx[1][o], Sxi = sSx[2][o];
                int t2 = r + o;
                float Syl, Syr, Syi;
                if (t2 < NOUTY) {
                    Syl = sSy[par][0][t2]; Syr = sSy[par][1][t2]; Syi = sSy[par][2][t2];
                } else {
                    int w = t2 - NOUTY;
                    Syl = sSy[par ^ 1][0][w]; Syr = sSy[par ^ 1][1][w]; Syi = sSy[par ^ 1][2][w];
                }
                accr += (Sxl + Syl + Sxr + Syr) / (Sxi + Syi + 1e-4f);
            }
        }
#pragma unroll
        for (int j = 0; j < 3; j++) Vy[j] = VyN[j];
        par ^= 1;
    }

    // ---- block reduction -> per-block slot ----
    const unsigned fm = 0xFFFFFFFFu;
#pragma unroll
    for (int off = 16; off; off >>= 1) {
        accr  += __shfl_down_sync(fm, accr,  off);
        accgx += __shfl_down_sync(fm, accgx, off);
        accgy += __shfl_down_sync(fm, accgy, off);
    }
    int wid = c >> 5, lane = c & 31;
    if (lane == 0) { sred[0][wid] = accr; sred[1][wid] = accgx; sred[2][wid] = accgy; }
    __syncthreads();
    if (wid == 0) {
        float a = (lane < 8) ? sred[0][lane] : 0.f;
        float b = (lane < 8) ? sred[1][lane] : 0.f;
        float d = (lane < 8) ? sred[2][lane] : 0.f;
#pragma unroll
        for (int off = 4; off; off >>= 1) {
            a += __shfl_down_sync(fm, a, off);
            b += __shfl_down_sync(fm, b, off);
            d += __shfl_down_sync(fm, d, off);
        }
        if (lane == 0) {
            g_part[blockIdx.x][0] = (double)a;
            g_part[blockIdx.x][1] = (double)b;
            g_part[blockIdx.x][2] = (double)d;
            __threadfence();
            s_rank = atomicAdd(&g_ctr, 1);
        }
    }
    __syncthreads();

    // ---- last block finalizes (and resets counter for next launch) ----
    if (s_rank == GRID - 1) {
        if (c == 0) g_ctr = 0;
        double a = 0.0, b = 0.0, d = 0.0;
        for (int s = c; s < GRID; s += 256) {
            a += g_part[s][0]; b += g_part[s][1]; d += g_part[s][2];
        }
#pragma unroll
        for (int off = 16; off; off >>= 1) {
            a += __shfl_down_sync(fm, a, off);
            b += __shfl_down_sync(fm, b, off);
            d += __shfl_down_sync(fm, d, off);
        }
        if (lane == 0) { dred[0][wid] = a; dred[1][wid] = b; dred[2][wid] = d; }
        __syncthreads();
        if (wid == 0) {
            a = (lane < 8) ? dred[0][lane] : 0.0;
            b = (lane < 8) ? dred[1][lane] : 0.0;
            d = (lane < 8) ? dred[2][lane] : 0.0;
#pragma unroll
            for (int off = 4; off; off >>= 1) {
                a += __shfl_down_sync(fm, a, off);
                b += __shfl_down_sync(fm, b, off);
                d += __shfl_down_sync(fm, d, off);
            }
            if (lane == 0) {
                double nnorm = (double)NPLANES * 502.0 * 503.0;
                double ngx   = (double)NPLANES * 511.0 * 512.0;
                double ngy   = (double)NPLANES * 512.0 * 511.0;
                out[0] = (float)(1e-4 * (a / nnorm) + b / ngx + d / ngy);
            }
        }
    }
}

extern "C" void kernel_launch(void* const* d_in, const int* in_sizes, int n_in,
                              void* d_out, int out_size) {
    const float* outl = (const float*)d_in[0];
    const float* outr = (const float*)d_in[1];
    const float* inpi = (const float*)d_in[2];
    float* out = (float*)d_out;

    // single launch per call: ncu (-s 5 -c 1) must land on this kernel.
    ktv_kernel<<<GRID, 256>>>(outl, outr, inpi, out);
}

// round 4
// speedup vs baseline: 1.3515x; 1.3515x over previous
#include <cuda_runtime.h>
#include <cuda_bf16.h>

#define Ww      512
#define HW      (512*512)
#define RROWS   21
#define CHUNKS  24
#define NPLANES 24
#define GRID    (NPLANES*CHUNKS)      // 576
#define XROWS   502                   // gx box rows
#define NOUTX   503                   // gx box cols
#define NOUTY   502                   // gy box cols
#define SPITCH  520

__device__ double g_part[GRID][3];    // ratio, gx, gy per block
__device__ unsigned int g_ctr = 0;    // last-block counter (self-resetting)

// running 10-sum, 13 outputs per thread, t in [0,39): stride 13 coprime to 32
// -> conflict-free. Max src index = 511 (arrays sized SPITCH>=512).
__device__ __forceinline__ void hsum13(const float* __restrict__ src,
                                       float* __restrict__ dst, int nOut, int t) {
    int base = 13 * t;
    if (base >= nOut) return;
    float s = 0.f;
#pragma unroll
    for (int k = 0; k < 10; k++) s += src[base + k];
#pragma unroll
    for (int u = 0; u < 13; u++) {
        int j = base + u;
        if (j >= nOut) break;
        dst[j] = s;
        if (u < 12 && j + 1 < nOut) s += src[j + 10] - src[j];
    }
}

__global__ __launch_bounds__(256, 4)
void ktv_kernel(const float* __restrict__ outl,
                const float* __restrict__ outr,
                const float* __restrict__ inpi,
                float* __restrict__ out) {
    __shared__ float sV[6][SPITCH];      // Vx L/R/I = 0..2, Vy L/R/I = 3..5
    __shared__ float sSx[3][SPITCH];
    __shared__ float sSy[2][3][SPITCH];
    __shared__ float sred[3][8];
    __shared__ double dred[3][8];
    __shared__ unsigned s_rank;

    const int plane = blockIdx.x / CHUNKS;
    const int chunk = blockIdx.x % CHUNKS;
    const int r0 = chunk * RROWS;
    const int r1 = min(r0 + RROWS, XROWS);
    const bool is_last = (r1 == XROWS);
    const float* __restrict__ base[3] = {
        outl + (size_t)plane * HW,
        outr + (size_t)plane * HW,
        inpi + (size_t)plane * HW };
    const int c = threadIdx.x;             // column pair (2c, 2c+1)
    const int x2i = (c < 255) ? (2 * c + 2) : 511;   // clamped col+2 index
    const bool cok = (c < 255);            // gy valid at col 2c+1

    float accr = 0.f, accgx = 0.f, accgy = 0.f;
    float2 Vx[3], Vy[3], p[3], l[3], pt[3];
    float  lx2[3], ptx2[3];
#pragma unroll
    for (int j = 0; j < 3; j++) { Vx[j] = make_float2(0.f, 0.f); Vy[j] = make_float2(0.f, 0.f); }

    // ---- bootstrap rows r0..r0+10 ----
#pragma unroll 1
    for (int k = 0; k <= 10; k++) {
        const int row = r0 + k;
        float2 v[3]; float x2[3];
#pragma unroll
        for (int j = 0; j < 3; j++) {
            const float* rp = base[j] + (size_t)row * Ww;
            v[j]  = reinterpret_cast<const float2*>(rp)[c];
            x2[j] = rp[x2i];
        }
        if (k > 0) {
            float2 g[3];
#pragma unroll
            for (int j = 0; j < 3; j++) {
                g[j].x = v[j].x - p[j].x; g[j].y = v[j].y - p[j].y;
                Vx[j].x += fabsf(g[j].x); Vx[j].y += fabsf(g[j].y);
            }
            int gr = row - 1;
            if ((gr >= r0 && gr < r1) || (is_last && gr >= XROWS))
                accgx += fabsf(g[0].x + g[1].x - g[2].x)
                       + fabsf(g[0].y + g[1].y - g[2].y);
        }
        float2 y[3];
#pragma unroll
        for (int j = 0; j < 3; j++) {
            y[j].x = v[j].y - v[j].x;
            y[j].y = x2[j] - v[j].y;
        }
        if (k < 10) {
#pragma unroll
            for (int j = 0; j < 3; j++) { Vy[j].x += fabsf(y[j].x); Vy[j].y += fabsf(y[j].y); }
        }
        if ((row >= r0 && row < r1) || (is_last && row >= XROWS)) {
            accgy += fabsf(y[0].x + y[1].x - y[2].x);
            if (cok) accgy += fabsf(y[0].y + y[1].y - y[2].y);
        }
#pragma unroll
        for (int j = 0; j < 3; j++) p[j] = v[j];
        if (k == 0)  { for (int j = 0; j < 3; j++) { pt[j] = v[j]; ptx2[j] = x2[j]; } }
        if (k == 10) { for (int j = 0; j < 3; j++) { l[j]  = v[j]; lx2[j]  = x2[j]; } }
    }

    // hsum Vy(r0) -> sSy[0]
#pragma unroll
    for (int j = 0; j < 3; j++)
        *reinterpret_cast<float2*>(&sV[3 + j][2 * c]) = Vy[j];
    __syncthreads();
    if (c < 117) hsum13(sV[3 + c / 39], sSy[0][c / 39], NOUTY, c % 39);
    __syncthreads();
    int par = 0;   // sSy[par] = S_y(row r)

    // ---- main loop over output x-rows ----
    for (int r = r0; r < r1; r++) {
        float2 VyN[3];
        if (r == r0) {
            // lead = bootstrap row r0+10 (l,lx2); trail = row r0 (pt,ptx2); Vx unchanged
#pragma unroll
            for (int j = 0; j < 3; j++) {
                float2 ty; ty.x = pt[j].y - pt[j].x; ty.y = ptx2[j] - pt[j].y;
                float2 yl; yl.x = l[j].y - l[j].x;   yl.y = lx2[j]  - l[j].y;
                VyN[j].x = Vy[j].x - fabsf(ty.x) + fabsf(yl.x);
                VyN[j].y = Vy[j].y - fabsf(ty.y) + fabsf(yl.y);
            }
        } else {
            float2 n[3], t1[3]; float nx2[3], t1x2[3];
#pragma unroll
            for (int j = 0; j < 3; j++) {
                const float* rpn = base[j] + (size_t)(r + 10) * Ww;
                const float* rpt = base[j] + (size_t)r * Ww;
                n[j]   = reinterpret_cast<const float2*>(rpn)[c];
                nx2[j] = rpn[x2i];
                t1[j]  = reinterpret_cast<const float2*>(rpt)[c];
                t1x2[j]= rpt[x2i];
            }
            float2 gl[3];
#pragma unroll
            for (int j = 0; j < 3; j++) {
                gl[j].x = n[j].x - l[j].x;  gl[j].y = n[j].y - l[j].y;
                float2 gt; gt.x = t1[j].x - pt[j].x; gt.y = t1[j].y - pt[j].y;
                Vx[j].x += fabsf(gl[j].x) - fabsf(gt.x);
                Vx[j].y += fabsf(gl[j].y) - fabsf(gt.y);
            }
            int g = r + 9;
            if ((g >= r0 && g < r1) || (is_last && g >= XROWS))
                accgx += fabsf(gl[0].x + gl[1].x - gl[2].x)
                       + fabsf(gl[0].y + gl[1].y - gl[2].y);
            float2 yl[3];
#pragma unroll
            for (int j = 0; j < 3; j++) {
                yl[j].x = n[j].y - n[j].x;   yl[j].y = nx2[j] - n[j].y;
                float2 ty; ty.x = t1[j].y - t1[j].x; ty.y = t1x2[j] - t1[j].y;
                VyN[j].x = Vy[j].x - fabsf(ty.x) + fabsf(yl[j].x);
                VyN[j].y = Vy[j].y - fabsf(ty.y) + fabsf(yl[j].y);
            }
            int gy = r + 10;
            if ((gy >= r0 && gy < r1) || (is_last && gy >= XROWS)) {
                accgy += fabsf(yl[0].x + yl[1].x - yl[2].x);
                if (cok) accgy += fabsf(yl[0].y + yl[1].y - yl[2].y);
            }
#pragma unroll
            for (int j = 0; j < 3; j++) { l[j] = n[j]; lx2[j] = nx2[j]; pt[j] = t1[j]; }
        }

#pragma unroll
        for (int j = 0; j < 3; j++) {
            *reinterpret_cast<float2*>(&sV[j][2 * c])     = Vx[j];
            *reinterpret_cast<float2*>(&sV[3 + j][2 * c]) = VyN[j];
        }
        __syncthreads();
        if (c < 234) {
            int a = c / 39, t = c % 39;
            if (a < 3) hsum13(sV[a], sSx[a], NOUTX, t);
            else       hsum13(sV[a], sSy[par ^ 1][a - 3], NOUTY, t);
        }
        __syncthreads();
#pragma unroll
        for (int oi = 0; oi < 2; oi++) {
            int o = c + oi * 256;
            if (o < NOUTX) {
                float Sxl = sSx[0][o], Sxr = sSx[1][o], Sxi = sSx[2][o];
                int t2 = r + o;
                float Syl, Syr, Syi;
                if (t2 < NOUTY) {
                    Syl = sSy[par][0][t2]; Syr = sSy[par][1][t2]; Syi = sSy[par][2][t2];
                } else {
                    int w = t2 - NOUTY;
                    Syl = sSy[par ^ 1][0][w]; Syr = sSy[par ^ 1][1][w]; Syi = sSy[par ^ 1][2][w];
                }
                accr += (Sxl + Syl + Sxr + Syr) / (Sxi + Syi + 1e-4f);
            }
        }
#pragma unroll
        for (int j = 0; j < 3; j++) Vy[j] = VyN[j];
        par ^= 1;
    }

    // ---- block reduction -> per-block slot ----
    const unsigned fm = 0xFFFFFFFFu;
#pragma unroll
    for (int off = 16; off; off >>= 1) {
        accr  += __shfl_down_sync(fm, accr,  off);
        accgx += __shfl_down_sync(fm, accgx, off);
        accgy += __shfl_down_sync(fm, accgy, off);
    }
    int wid = c >> 5, lane = c & 31;
    if (lane == 0) { sred[0][wid] = accr; sred[1][wid] = accgx; sred[2][wid] = accgy; }
    __syncthreads();
    if (wid == 0) {
        float a = (lane < 8) ? sred[0][lane] : 0.f;
        float b = (lane < 8) ? sred[1][lane] : 0.f;
        float d = (lane < 8) ? sred[2][lane] : 0.f;
#pragma unroll
        for (int off = 4; off; off >>= 1) {
            a += __shfl_down_sync(fm, a, off);
            b += __shfl_down_sync(fm, b, off);
            d += __shfl_down_sync(fm, d, off);
        }
        if (lane == 0) {
            g_part[blockIdx.x][0] = (double)a;
            g_part[blockIdx.x][1] = (double)b;
            g_part[blockIdx.x][2] = (double)d;
            __threadfence();
            s_rank = atomicAdd(&g_ctr, 1);
        }
    }
    __syncthreads();

    // ---- last block finalizes (and resets counter for next launch) ----
    if (s_rank == GRID - 1) {
        if (c == 0) g_ctr = 0;
        double a = 0.0, b = 0.0, d = 0.0;
        for (int s = c; s < GRID; s += 256) {
            a += g_part[s][0]; b += g_part[s][1]; d += g_part[s][2];
        }
#pragma unroll
        for (int off = 16; off; off >>= 1) {
            a += __shfl_down_sync(fm, a, off);
            b += __shfl_down_sync(fm, b, off);
            d += __shfl_down_sync(fm, d, off);
        }
        if (lane == 0) { dred[0][wid] = a; dred[1][wid] = b; dred[2][wid] = d; }
        __syncthreads();
        if (wid == 0) {
            a = (lane < 8) ? dred[0][lane] : 0.0;
            b = (lane < 8) ? dred[1][lane] : 0.0;
            d = (lane < 8) ? dred[2][lane] : 0.0;
#pragma unroll
            for (int off = 4; off; off >>= 1) {
                a += __shfl_down_sync(fm, a, off);
                b += __shfl_down_sync(fm, b, off);
                d += __shfl_down_sync(fm, d, off);
            }
            if (lane == 0) {
                double nnorm = (double)NPLANES * 502.0 * 503.0;
                double ngx   = (double)NPLANES * 511.0 * 512.0;
                double ngy   = (double)NPLANES * 512.0 * 511.0;
                out[0] = (float)(1e-4 * (a / nnorm) + b / ngx + d / ngy);
            }
        }
    }
}

extern "C" void kernel_launch(void* const* d_in, const int* in_sizes, int n_in,
                              void* d_out, int out_size) {
    const float* outl = (const float*)d_in[0];
    const float* outr = (const float*)d_in[1];
    const float* inpi = (const float*)d_in[2];
    float* out = (float*)d_out;

    ktv_kernel<<<GRID, 256>>>(outl, outr, inpi, out);
}